// round 4
// baseline (speedup 1.0000x reference)
#include <cuda_runtime.h>

#define NPTS   4096
#define DOUT   3
#define IBLK   128
#define JCHUNK 128
#define NIB    (NPTS / IBLK)    // 32
#define NJB    (NPTS / JCHUNK)  // 32

// Scratch (allocation-free rule: __device__ globals)
__device__ float4 g_q[NPTS];          // scaled query projections {F0,F1,F2,_}
__device__ float4 g_j[2 * NPTS];      // per-j: [2j]={Ft0,Ft1,Ft2,_} [2j+1]={Y0,Y1,Y2,_}
__device__ float  g_num[NPTS * DOUT];
__device__ float  g_den[NPTS * DOUT];

__device__ __forceinline__ float ex2f(float x) {
    float y;
    asm("ex2.approx.ftz.f32 %0, %1;" : "=f"(y) : "f"(x));
    return y;
}

// Identical projection code path for x and train_X so that row i of both is
// bitwise-equal -> self-pair kernel value is exactly 1.0 (removed in finalize).
__device__ __forceinline__ void proj3(float4 v, const float* __restrict__ w, float s,
                                      float& f0, float& f1, float& f2) {
    f0 = (v.x * w[0] + v.y * w[1] + v.z * w[2]  + v.w * w[3])  * s;
    f1 = (v.x * w[4] + v.y * w[5] + v.z * w[6]  + v.w * w[7])  * s;
    f2 = (v.x * w[8] + v.y * w[9] + v.z * w[10] + v.w * w[11]) * s;
}

__global__ void proj_kernel(const float* __restrict__ x,
                            const float* __restrict__ tx,
                            const float* __restrict__ Y,
                            const float* __restrict__ W,
                            const float* __restrict__ h) {
    int i = blockIdx.x * blockDim.x + threadIdx.x;
    if (i >= NPTS) return;

    // exp(-0.5*((a-b)/h)^2) = ex2(-(c*(a-b))^2), c = sqrt(0.5*log2(e))/h
    float s = 0.8493218002880191f / h[0];

    float w[12];
#pragma unroll
    for (int k = 0; k < 12; k++) w[k] = __ldg(&W[k]);

    float4 xv = reinterpret_cast<const float4*>(x)[i];
    float4 tv = reinterpret_cast<const float4*>(tx)[i];

    float q0, q1, q2, t0, t1, t2;
    proj3(xv, w, s, q0, q1, q2);
    proj3(tv, w, s, t0, t1, t2);

    g_q[i] = make_float4(q0, q1, q2, 0.0f);
    g_j[2 * i]     = make_float4(t0, t1, t2, 0.0f);
    g_j[2 * i + 1] = make_float4(Y[i * 3 + 0], Y[i * 3 + 1], Y[i * 3 + 2], 0.0f);

    // zero accumulators (must be reset on every graph replay)
#pragma unroll
    for (int c = 0; c < DOUT; c++) {
        g_num[i * DOUT + c] = 0.0f;
        g_den[i * DOUT + c] = 0.0f;
    }
}

__global__ void __launch_bounds__(IBLK) pair_kernel() {
    __shared__ float4 sh[2 * JCHUNK];  // 4 KB

    int tid = threadIdx.x;
    int i   = blockIdx.x * IBLK + tid;
    int j0  = blockIdx.y * JCHUNK;

    // Stage this j-chunk's {F, Y} pairs (256 float4, 128 threads -> 2 each)
#pragma unroll
    for (int t = tid; t < 2 * JCHUNK; t += IBLK) sh[t] = g_j[2 * j0 + t];

    float4 q = g_q[i];
    float n0 = 0.f, n1 = 0.f, n2 = 0.f;
    float d0 = 0.f, d1 = 0.f, d2 = 0.f;

    __syncthreads();

#pragma unroll 8
    for (int j = 0; j < JCHUNK; j++) {
        float4 f  = sh[2 * j];      // broadcast LDS.128
        float4 yv = sh[2 * j + 1];  // broadcast LDS.128
        float u0 = f.x - q.x;  float k0 = ex2f(-u0 * u0);
        float u1 = f.y - q.y;  float k1 = ex2f(-u1 * u1);
        float u2 = f.z - q.z;  float k2 = ex2f(-u2 * u2);
        n0 = fmaf(k0, yv.x, n0);  d0 += k0;
        n1 = fmaf(k1, yv.y, n1);  d1 += k1;
        n2 = fmaf(k2, yv.z, n2);  d2 += k2;
    }

    atomicAdd(&g_num[i * DOUT + 0], n0);
    atomicAdd(&g_num[i * DOUT + 1], n1);
    atomicAdd(&g_num[i * DOUT + 2], n2);
    atomicAdd(&g_den[i * DOUT + 0], d0);
    atomicAdd(&g_den[i * DOUT + 1], d1);
    atomicAdd(&g_den[i * DOUT + 2], d2);
}

__global__ void finalize_kernel(const float* __restrict__ Y, float* __restrict__ out) {
    int i = blockIdx.x * blockDim.x + threadIdx.x;
    if (i >= NPTS) return;
#pragma unroll
    for (int c = 0; c < DOUT; c++) {
        // remove exact self-pair contribution (K_ii == 1.0 bitwise)
        float num = g_num[i * DOUT + c] - Y[i * DOUT + c];
        float den = g_den[i * DOUT + c] - 1.0f;
        out[i * DOUT + c] = num / den;
    }
}

extern "C" void kernel_launch(void* const* d_in, const int* in_sizes, int n_in,
                              void* d_out, int out_size) {
    const float* x  = (const float*)d_in[0];
    const float* tx = (const float*)d_in[1];
    const float* Y  = (const float*)d_in[2];
    const float* W  = (const float*)d_in[3];
    const float* h  = (const float*)d_in[4];
    float* out = (float*)d_out;

    proj_kernel<<<(NPTS + 255) / 256, 256>>>(x, tx, Y, W, h);
    pair_kernel<<<dim3(NIB, NJB), IBLK>>>();
    finalize_kernel<<<(NPTS + 255) / 256, 256>>>(Y, out);
}